// round 3
// baseline (speedup 1.0000x reference)
#include <cuda_runtime.h>

// Problem constants (fixed by the reference)
#define BB 16
#define NN 1024
#define DD 1024
#define UU 512

// Scratch (no cudaMalloc allowed)
__device__ float g_v[2 * DD];        // v_h | v_m
__device__ float g_c[2];             // c_h, c_m + b_out
__device__ float g_s[2 * BB * NN];   // sH | sM

// ---------------------------------------------------------------------------
// Kernel 1: v_h[d] = sum_u w_out[u]*W_h[u,d]; v_m likewise.
// Grid: 8 blocks x 256 threads -> 2048 outputs. W reads are fully coalesced
// (consecutive d across lanes), w_out[u] is an L1-hit broadcast.
// ---------------------------------------------------------------------------
__global__ void vkern(const float* __restrict__ W_h,
                      const float* __restrict__ W_m,
                      const float* __restrict__ w_out) {
    int gid = blockIdx.x * blockDim.x + threadIdx.x;   // 0..2047
    const float* __restrict__ W = (gid < DD) ? W_h : W_m;
    int d = gid & (DD - 1);
    float acc = 0.f;
#pragma unroll 8
    for (int u = 0; u < UU; ++u) {
        acc = fmaf(w_out[u], W[u * DD + d], acc);
    }
    g_v[gid] = acc;
}

// ---------------------------------------------------------------------------
// Kernel 2: c_h = w_out.b_h ; c_m = w_out.b_m + b_out. One block, 512 threads.
// ---------------------------------------------------------------------------
__global__ void ckern(const float* __restrict__ b_h,
                      const float* __restrict__ b_m,
                      const float* __restrict__ w_out,
                      const float* __restrict__ b_out) {
    __shared__ float sh[UU], sm[UU];
    int t = threadIdx.x;
    float w = w_out[t];
    sh[t] = w * b_h[t];
    sm[t] = w * b_m[t];
    __syncthreads();
    for (int s = UU / 2; s > 0; s >>= 1) {
        if (t < s) { sh[t] += sh[t + s]; sm[t] += sm[t + s]; }
        __syncthreads();
    }
    if (t == 0) {
        g_c[0] = sh[0];
        g_c[1] = sm[0] + b_out[0];
    }
}

// ---------------------------------------------------------------------------
// Kernel 3: per row (b,n): sH = x_row . v_h + c_h ; sM = x_row . v_m + c_m.
// One block (256 threads) per row; each thread owns one float4 of the row.
// x read is the dominant 64 MB stream, fully coalesced 16B/lane.
// ---------------------------------------------------------------------------
__global__ void __launch_bounds__(256) skern(const float* __restrict__ x) {
    int row = blockIdx.x;                       // b*N + n, 0..16383
    int t = threadIdx.x;                        // 0..255
    const float4* __restrict__ x4  = (const float4*)(x + (size_t)row * DD);
    const float4* __restrict__ vh4 = (const float4*)(g_v);
    const float4* __restrict__ vm4 = (const float4*)(g_v + DD);

    float4 xv = x4[t];
    float4 vh = vh4[t];
    float4 vm = vm4[t];

    float ah = xv.x * vh.x + xv.y * vh.y + xv.z * vh.z + xv.w * vh.w;
    float am = xv.x * vm.x + xv.y * vm.y + xv.z * vm.z + xv.w * vm.w;

#pragma unroll
    for (int o = 16; o > 0; o >>= 1) {
        ah += __shfl_xor_sync(0xffffffffu, ah, o);
        am += __shfl_xor_sync(0xffffffffu, am, o);
    }

    __shared__ float rh[8], rm[8];
    if ((t & 31) == 0) { rh[t >> 5] = ah; rm[t >> 5] = am; }
    __syncthreads();

    if (t < 32) {
        float h = (t < 8) ? rh[t] : 0.f;
        float m = (t < 8) ? rm[t] : 0.f;
#pragma unroll
        for (int o = 4; o > 0; o >>= 1) {
            h += __shfl_xor_sync(0xffffffffu, h, o);
            m += __shfl_xor_sync(0xffffffffu, m, o);
        }
        if (t == 0) {
            g_s[row]           = h + g_c[0];
            g_s[BB * NN + row] = m + g_c[1];
        }
    }
}

// ---------------------------------------------------------------------------
// Kernel 4: scores[b,i,j] = sH[b,i] + sM[b,j]. One block per (b,i) row,
// each thread stores one float4 (j..j+3). sM rows (4 KB/batch) stay L2-hot;
// the 64 MB output write is the stream.
// ---------------------------------------------------------------------------
__global__ void __launch_bounds__(256) outkern(float* __restrict__ out) {
    int bi = blockIdx.x;            // b*N + i
    int b  = bi >> 10;              // N = 1024
    float sH = g_s[bi];
    const float4* __restrict__ sM4 = (const float4*)(g_s + BB * NN + b * NN);
    float4 m = sM4[threadIdx.x];
    float4 r = make_float4(sH + m.x, sH + m.y, sH + m.z, sH + m.w);
    ((float4*)out)[(size_t)bi * (NN / 4) + threadIdx.x] = r;
}

// ---------------------------------------------------------------------------
// Inputs (metadata order): x, W_h, b_h, W_m, b_m, w_out, b_out
// Output: float32 [B, N, N]
// ---------------------------------------------------------------------------
extern "C" void kernel_launch(void* const* d_in, const int* in_sizes, int n_in,
                              void* d_out, int out_size) {
    const float* x     = (const float*)d_in[0];
    const float* W_h   = (const float*)d_in[1];
    const float* b_h   = (const float*)d_in[2];
    const float* W_m   = (const float*)d_in[3];
    const float* b_m   = (const float*)d_in[4];
    const float* w_out = (const float*)d_in[5];
    const float* b_out = (const float*)d_in[6];
    float* out = (float*)d_out;

    vkern<<<(2 * DD) / 256, 256>>>(W_h, W_m, w_out);
    ckern<<<1, UU>>>(b_h, b_m, w_out, b_out);
    skern<<<BB * NN, 256>>>(x);
    outkern<<<BB * NN, 256>>>(out);
}

// round 4
// speedup vs baseline: 2.2176x; 2.2176x over previous
#include <cuda_runtime.h>

// Problem constants (fixed by the reference)
#define BB 16
#define NN 1024
#define DD 1024
#define UU 512

#define SPLITS 64
#define UCHUNK (UU / SPLITS)   // 8

// Scratch (no cudaMalloc allowed)
__device__ float g_part[SPLITS * 2 * DD];  // partial v sums [split][2*D]
__device__ float g_v[2 * DD];              // v_h | v_m
__device__ float g_c[2];                   // c_h, c_m + b_out
__device__ float g_s[2 * BB * NN];         // sH | sM

// ---------------------------------------------------------------------------
// Kernel 1: partial sums of v[col] = sum_u w_out[u]*W[u,col] over 8-u chunks.
// Blocks 0..511: 512 blocks x 256 threads = 131072 threads = 2048 cols x 64
// splits. Coalesced 128B warp reads of W; w_out is a broadcast hit.
// Block 512: computes the scalar constants c_h = w.b_h, c_m = w.b_m + b_out.
// ---------------------------------------------------------------------------
__global__ void __launch_bounds__(256) vpart(const float* __restrict__ W_h,
                                             const float* __restrict__ W_m,
                                             const float* __restrict__ w_out,
                                             const float* __restrict__ b_h,
                                             const float* __restrict__ b_m,
                                             const float* __restrict__ b_out) {
    if (blockIdx.x == 512) {
        // bias constants: 256 threads, 2 u's each, then block reduce
        int t = threadIdx.x;
        float w0 = w_out[t], w1 = w_out[t + 256];
        float h = w0 * b_h[t] + w1 * b_h[t + 256];
        float m = w0 * b_m[t] + w1 * b_m[t + 256];
#pragma unroll
        for (int o = 16; o > 0; o >>= 1) {
            h += __shfl_xor_sync(0xffffffffu, h, o);
            m += __shfl_xor_sync(0xffffffffu, m, o);
        }
        __shared__ float rh[8], rm[8];
        if ((t & 31) == 0) { rh[t >> 5] = h; rm[t >> 5] = m; }
        __syncthreads();
        if (t == 0) {
            float hh = 0.f, mm = 0.f;
#pragma unroll
            for (int k = 0; k < 8; ++k) { hh += rh[k]; mm += rm[k]; }
            g_c[0] = hh;
            g_c[1] = mm + b_out[0];
        }
        return;
    }

    int gid = blockIdx.x * 256 + threadIdx.x;  // 0..131071
    int col = gid & (2 * DD - 1);              // 0..2047
    int s   = gid >> 11;                       // split 0..63
    const float* __restrict__ W = (col < DD) ? W_h : W_m;
    int d  = col & (DD - 1);
    int u0 = s * UCHUNK;
    float acc = 0.f;
#pragma unroll
    for (int k = 0; k < UCHUNK; ++k)
        acc = fmaf(w_out[u0 + k], W[(size_t)(u0 + k) * DD + d], acc);
    g_part[s * (2 * DD) + col] = acc;
}

// ---------------------------------------------------------------------------
// Kernel 2: reduce the 64 partials per column (fixed order -> deterministic).
// 8 blocks x 256 threads; all reads coalesced, 512 KB, L2-hot.
// ---------------------------------------------------------------------------
__global__ void __launch_bounds__(256) vreduce() {
    int col = blockIdx.x * 256 + threadIdx.x;  // 0..2047
    float acc = 0.f;
#pragma unroll
    for (int s = 0; s < SPLITS; ++s)
        acc += g_part[s * (2 * DD) + col];
    g_v[col] = acc;
}

// ---------------------------------------------------------------------------
// Kernel 3: per row (b,n): sH = x_row.v_h + c_h ; sM = x_row.v_m + c_m.
// One WARP per row: 8 float4 x-loads per thread (MLP=8), shuffle-only
// reduction, no block barrier. Block = 256 thr = 8 rows; grid = 2048.
// g_v (8 KB) stays L1-resident after the first warp touches it.
// ---------------------------------------------------------------------------
__global__ void __launch_bounds__(256) skern(const float* __restrict__ x) {
    int warp = blockIdx.x * 8 + (threadIdx.x >> 5);  // row = b*N + n
    int lane = threadIdx.x & 31;
    const float4* __restrict__ x4  = (const float4*)(x + (size_t)warp * DD);
    const float4* __restrict__ vh4 = (const float4*)(g_v);
    const float4* __restrict__ vm4 = (const float4*)(g_v + DD);

    float ah = 0.f, am = 0.f;
#pragma unroll
    for (int k = 0; k < 8; ++k) {
        int idx = lane + 32 * k;
        float4 xv = x4[idx];
        float4 vh = vh4[idx];
        float4 vm = vm4[idx];
        ah += xv.x * vh.x + xv.y * vh.y + xv.z * vh.z + xv.w * vh.w;
        am += xv.x * vm.x + xv.y * vm.y + xv.z * vm.z + xv.w * vm.w;
    }
#pragma unroll
    for (int o = 16; o > 0; o >>= 1) {
        ah += __shfl_xor_sync(0xffffffffu, ah, o);
        am += __shfl_xor_sync(0xffffffffu, am, o);
    }
    if (lane == 0) {
        g_s[warp]           = ah + g_c[0];
        g_s[BB * NN + warp] = am + g_c[1];
    }
}

// ---------------------------------------------------------------------------
// Kernel 4: scores[b,i,j] = sH[b,i] + sM[b,j]. 8 output rows per block:
// thread t loads its sM float4 once, then issues 8 independent float4
// stores (store MLP=8). Grid = 2048. Rows i0..i0+7 share one batch b
// (8 divides N), so one sM vector serves all 8 rows.
// ---------------------------------------------------------------------------
__global__ void __launch_bounds__(256) outkern(float* __restrict__ out) {
    int i0 = blockIdx.x * 8;   // first (b*N + i) row of this block
    int b  = i0 >> 10;         // N = 1024
    int t  = threadIdx.x;
    float4 m = ((const float4*)(g_s + BB * NN + b * NN))[t];

    float sH[8];
#pragma unroll
    for (int r = 0; r < 8; ++r) sH[r] = g_s[i0 + r];

    float4* __restrict__ o4 = (float4*)out;
#pragma unroll
    for (int r = 0; r < 8; ++r) {
        float4 v = make_float4(sH[r] + m.x, sH[r] + m.y,
                               sH[r] + m.z, sH[r] + m.w);
        o4[(size_t)(i0 + r) * (NN / 4) + t] = v;
    }
}

// ---------------------------------------------------------------------------
// Inputs (metadata order): x, W_h, b_h, W_m, b_m, w_out, b_out
// Output: float32 [B, N, N]
// ---------------------------------------------------------------------------
extern "C" void kernel_launch(void* const* d_in, const int* in_sizes, int n_in,
                              void* d_out, int out_size) {
    const float* x     = (const float*)d_in[0];
    const float* W_h   = (const float*)d_in[1];
    const float* b_h   = (const float*)d_in[2];
    const float* W_m   = (const float*)d_in[3];
    const float* b_m   = (const float*)d_in[4];
    const float* w_out = (const float*)d_in[5];
    const float* b_out = (const float*)d_in[6];
    float* out = (float*)d_out;

    vpart<<<513, 256>>>(W_h, W_m, w_out, b_h, b_m, b_out);
    vreduce<<<8, 256>>>();
    skern<<<BB * NN / 8, 256>>>(x);
    outkern<<<BB * NN / 8, 256>>>(out);
}